// round 3
// baseline (speedup 1.0000x reference)
#include <cuda_runtime.h>
#include <cuda_bf16.h>

namespace {

constexpr int Bc = 2, Hc = 16, Sc = 2048, Dc = 64;
constexpr int BM = 16;     // query rows per block
constexpr int BN = 128;    // key tile
constexpr int NT = 256;    // threads per block
constexpr float NEGV = -1e9f;
constexpr int DP = Dc + 4; // padded smem row

struct Smem {
    float scores[BM][Sc];   // 128 KB, reused as probabilities
    float q[BM][DP];        // 4.25 KB
    float k[BN][DP];        // 34 KB
};

__global__ void __launch_bounds__(NT, 1)
attn_kernel(const float* __restrict__ gq,
            const float* __restrict__ gk,
            const float* __restrict__ gv,
            const int*   __restrict__ gmask,
            float* __restrict__ gout,    // [B,H,S,D] or null
            float* __restrict__ gattn)   // [B,H,S,S] or null
{
    extern __shared__ char smem_raw[];
    Smem& sm = *reinterpret_cast<Smem*>(smem_raw);

    const int bh  = blockIdx.y;           // 0..B*H-1
    const int q0  = blockIdx.x * BM;      // query tile start
    const int tid = threadIdx.x;
    const size_t base = (size_t)bh * Sc * Dc;   // q/k/v/out all [BH, S, D]

    // ---- load Q tile -------------------------------------------------------
    for (int i = tid; i < BM * Dc; i += NT) {
        int r = i / Dc, c = i % Dc;
        sm.q[r][c] = gq[base + (size_t)(q0 + r) * Dc + c];
    }

    const int qi = tid & 15;     // query row handled by this thread
    const int kg = tid >> 4;     // key group (8 keys) / d group (4 dims)
    const float inv_temp = 0.125f;  // 1/sqrt(64)

    // ---- S = Q K^T / temp, masked, into smem scores ------------------------
    for (int kt = 0; kt < Sc / BN; ++kt) {
        __syncthreads();   // previous tile's compute done before K reload
        for (int i = tid; i < BN * Dc; i += NT) {
            int r = i / Dc, c = i % Dc;
            sm.k[r][c] = gk[base + (size_t)(kt * BN + r) * Dc + c];
        }
        __syncthreads();

        float acc[8];
        #pragma unroll
        for (int u = 0; u < 8; ++u) acc[u] = 0.f;

        #pragma unroll
        for (int d0 = 0; d0 < Dc; d0 += 4) {
            float4 qv = *reinterpret_cast<const float4*>(&sm.q[qi][d0]);
            #pragma unroll
            for (int u = 0; u < 8; ++u) {
                float4 kv = *reinterpret_cast<const float4*>(&sm.k[kg * 8 + u][d0]);
                acc[u] = fmaf(qv.x, kv.x, acc[u]);
                acc[u] = fmaf(qv.y, kv.y, acc[u]);
                acc[u] = fmaf(qv.z, kv.z, acc[u]);
                acc[u] = fmaf(qv.w, kv.w, acc[u]);
            }
        }

        const int jbase = kt * BN + kg * 8;
        const size_t mrow = (size_t)(q0 + qi) * Sc;
        #pragma unroll
        for (int u = 0; u < 8; ++u) {
            int j = jbase + u;
            int m = gmask[mrow + j];
            sm.scores[qi][j] = (m == 0) ? NEGV : acc[u] * inv_temp;
        }
    }
    __syncthreads();

    // ---- row softmax (warp w owns rows 2w, 2w+1) ---------------------------
    {
        const int lane = tid & 31, w = tid >> 5;
        #pragma unroll
        for (int rr = 0; rr < 2; ++rr) {
            const int r = w * 2 + rr;
            float m = -3.4e38f;
            for (int i = lane; i < Sc; i += 32)
                m = fmaxf(m, sm.scores[r][i]);
            #pragma unroll
            for (int o = 16; o; o >>= 1)
                m = fmaxf(m, __shfl_xor_sync(0xffffffffu, m, o));

            float l = 0.f;
            for (int i = lane; i < Sc; i += 32) {
                float p = __expf(sm.scores[r][i] - m);
                sm.scores[r][i] = p;
                l += p;
            }
            #pragma unroll
            for (int o = 16; o; o >>= 1)
                l += __shfl_xor_sync(0xffffffffu, l, o);
            const float inv = 1.f / l;

            float4* arow = gattn
                ? reinterpret_cast<float4*>(gattn + ((size_t)bh * Sc + (q0 + r)) * Sc)
                : nullptr;
            float4* srow = reinterpret_cast<float4*>(sm.scores[r]);
            for (int i = lane; i < Sc / 4; i += 32) {
                float4 p4 = srow[i];
                p4.x *= inv; p4.y *= inv; p4.z *= inv; p4.w *= inv;
                srow[i] = p4;
                if (arow) arow[i] = p4;
            }
        }
    }
    __syncthreads();

    // ---- O = P V  (thread: row qi, dims kg*4..kg*4+3) ----------------------
    if (gout) {
        float4 o = make_float4(0.f, 0.f, 0.f, 0.f);
        const float* vb = gv + base + (size_t)kg * 4;
        const float* prow = sm.scores[qi];
        for (int k0 = 0; k0 < Sc; k0 += 4) {
            float4 p4 = *reinterpret_cast<const float4*>(&prow[k0]);
            float4 v0 = *reinterpret_cast<const float4*>(&vb[(size_t)(k0 + 0) * Dc]);
            float4 v1 = *reinterpret_cast<const float4*>(&vb[(size_t)(k0 + 1) * Dc]);
            float4 v2 = *reinterpret_cast<const float4*>(&vb[(size_t)(k0 + 2) * Dc]);
            float4 v3 = *reinterpret_cast<const float4*>(&vb[(size_t)(k0 + 3) * Dc]);
            o.x = fmaf(p4.x, v0.x, o.x); o.y = fmaf(p4.x, v0.y, o.y);
            o.z = fmaf(p4.x, v0.z, o.z); o.w = fmaf(p4.x, v0.w, o.w);
            o.x = fmaf(p4.y, v1.x, o.x); o.y = fmaf(p4.y, v1.y, o.y);
            o.z = fmaf(p4.y, v1.z, o.z); o.w = fmaf(p4.y, v1.w, o.w);
            o.x = fmaf(p4.z, v2.x, o.x); o.y = fmaf(p4.z, v2.y, o.y);
            o.z = fmaf(p4.z, v2.z, o.z); o.w = fmaf(p4.z, v2.w, o.w);
            o.x = fmaf(p4.w, v3.x, o.x); o.y = fmaf(p4.w, v3.y, o.y);
            o.z = fmaf(p4.w, v3.z, o.z); o.w = fmaf(p4.w, v3.w, o.w);
        }
        *reinterpret_cast<float4*>(
            gout + base + (size_t)(q0 + qi) * Dc + kg * 4) = o;
    }
}

} // namespace

extern "C" void kernel_launch(void* const* d_in, const int* in_sizes, int n_in,
                              void* d_out, int out_size)
{
    const float* q    = (const float*)d_in[0];
    const float* k    = (const float*)d_in[1];
    const float* v    = (const float*)d_in[2];
    const int*   mask = (const int*)d_in[3];

    const size_t nOut  = (size_t)Bc * Hc * Sc * Dc;   // 4,194,304
    const size_t nAttn = (size_t)Bc * Hc * Sc * Sc;   // 134,217,728

    float* outp  = nullptr;
    float* attnp = nullptr;
    float* base  = (float*)d_out;
    if ((size_t)out_size >= nOut + nAttn) {           // tuple (output, attn)
        outp  = base;
        attnp = base + nOut;
    } else if ((size_t)out_size == nAttn) {           // attn only
        attnp = base;
    } else {                                          // output only
        outp = base;
    }

    cudaFuncSetAttribute(attn_kernel,
                         cudaFuncAttributeMaxDynamicSharedMemorySize,
                         (int)sizeof(Smem));

    dim3 grid(Sc / BM, Bc * Hc);   // (128, 32)
    attn_kernel<<<grid, NT, sizeof(Smem)>>>(q, k, v, mask, outp, attnp);
}